// round 11
// baseline (speedup 1.0000x reference)
#include <cuda_runtime.h>
#include <cuda_fp16.h>
#include <cstdint>

#define NNODES 50000
#define NEDGES 600000
#define NB     ((NNODES + 255) / 256)   /* 196 scan blocks */
#define SR     68    /* smem row stride in words: row starts quad-aligned banks */
#define GEMM_SMEM ((128 * SR + 128 * SR) * 4)   /* xs + wh = 69632 bytes */

// ---------------- scratch (static device globals; no allocation) -------------
__device__ __align__(16) uint32_t g_h1h [NNODES * 64];  // x@W1, half2 packed
__device__ __align__(16) uint32_t g_h1bh[NNODES * 64];  // relu layer-1 out, half2
__device__ __align__(16) uint32_t g_h2h [NNODES * 20];  // h1b@W2, half2
__device__ float g_dinv[NNODES];
__device__ int   g_degi[NNODES];           // zero-init; re-zeroed by scan
__device__ int   g_rowstart[NNODES + 1];
__device__ int   g_cursor[NNODES];
__device__ __align__(8) int2 g_csr[NEDGES];   // (src, nrm fp32 bits)
// decoupled-lookback state (zero-init; reset by csrfill each replay)
__device__ int                g_ticket;
__device__ unsigned long long g_packed[NB];  // (flag<<32)|value; 1=agg, 2=prefix

// ---------------- helpers ------------------------------------------------------
__device__ __forceinline__ uint32_t pkh2(float a, float b) {
    __half2 h = __floats2half2_rn(a, b);
    return *reinterpret_cast<uint32_t*>(&h);
}
__device__ __forceinline__ float2 h2f2(uint32_t u) {
    __half2 h = *reinterpret_cast<__half2*>(&u);
    return __half22float2(h);
}
__device__ __forceinline__ void mma_f16(
    float& d0, float& d1, float& d2, float& d3,
    uint32_t a0, uint32_t a1, uint32_t a2, uint32_t a3,
    uint32_t b0, uint32_t b1)
{
    asm volatile(
        "mma.sync.aligned.m16n8k16.row.col.f32.f16.f16.f32 "
        "{%0,%1,%2,%3}, {%4,%5,%6,%7}, {%8,%9}, {%0,%1,%2,%3};"
        : "+f"(d0), "+f"(d1), "+f"(d2), "+f"(d3)
        : "r"(a0), "r"(a1), "r"(a2), "r"(a3), "r"(b0), "r"(b1));
}
__device__ __forceinline__ void ldsm_x4(
    uint32_t& r0, uint32_t& r1, uint32_t& r2, uint32_t& r3, uint32_t addr)
{
    asm volatile("ldmatrix.sync.aligned.m8n8.x4.shared.b16 {%0,%1,%2,%3}, [%4];"
        : "=r"(r0), "=r"(r1), "=r"(r2), "=r"(r3) : "r"(addr));
}
__device__ __forceinline__ void ldsm_x4t(
    uint32_t& r0, uint32_t& r1, uint32_t& r2, uint32_t& r3, uint32_t addr)
{
    asm volatile("ldmatrix.sync.aligned.m8n8.x4.trans.shared.b16 {%0,%1,%2,%3}, [%4];"
        : "=r"(r0), "=r"(r1), "=r"(r2), "=r"(r3) : "r"(addr));
}
__device__ __forceinline__ void acc8(float* acc, uint4 u, float n) {
    float2 a;
    a = h2f2(u.x); acc[0] = fmaf(n, a.x, acc[0]); acc[1] = fmaf(n, a.y, acc[1]);
    a = h2f2(u.y); acc[2] = fmaf(n, a.x, acc[2]); acc[3] = fmaf(n, a.y, acc[3]);
    a = h2f2(u.z); acc[4] = fmaf(n, a.x, acc[4]); acc[5] = fmaf(n, a.y, acc[5]);
    a = h2f2(u.w); acc[6] = fmaf(n, a.x, acc[6]); acc[7] = fmaf(n, a.y, acc[7]);
}

// ---------------- degree (2 edges per thread) ---------------------------------
__global__ void degree_kernel(const int* __restrict__ ei) {
    int e2 = blockIdx.x * blockDim.x + threadIdx.x;
    if (e2 * 2 >= NEDGES) return;
    int2 d = *(const int2*)&ei[NEDGES + e2 * 2];
    atomicAdd(&g_degi[d.x], 1);
    atomicAdd(&g_degi[d.y], 1);
}

// ---------------- fused scan: dinv + rowstart + cursor (warp lookback) --------
__global__ __launch_bounds__(256) void scan_fused_kernel() {
    __shared__ int s[256];
    __shared__ int sh_bid;
    __shared__ int sh_prefix;

    int t = threadIdx.x;
    if (t == 0) sh_bid = atomicAdd(&g_ticket, 1);
    __syncthreads();
    int b   = sh_bid;
    int gid = b * 256 + t;

    int d = (gid < NNODES) ? g_degi[gid] : 0;
    if (gid < NNODES) {
        g_dinv[gid] = rsqrtf((float)d + 1.0f);
        g_degi[gid] = 0;                       // reset for next replay
    }
    s[t] = d;
    __syncthreads();
#pragma unroll
    for (int off = 1; off < 256; off <<= 1) {
        int v = (t >= off) ? s[t - off] : 0;
        __syncthreads();
        if (t >= off) s[t] += v;
        __syncthreads();
    }
    int incl = s[t];
    int aggregate = s[255];

    if (t == 0)
        atomicExch(&g_packed[b], (1ULL << 32) | (unsigned)aggregate);

    if (t < 32) {   // warp 0: parallel lookback
        int run = 0;
        int p = b - 1;
        while (p >= 0) {
            int idx = p - t;
            unsigned long long v = 0ULL;
            if (idx >= 0) {
                do { v = *((volatile unsigned long long*)&g_packed[idx]); }
                while ((v >> 32) == 0ULL);
            }
            unsigned flag = (unsigned)(v >> 32);
            unsigned val  = (unsigned)v;
            unsigned ball = __ballot_sync(0xffffffffu, flag == 2u);
            int lp = ball ? (__ffs(ball) - 1) : 32;
            if (t > lp) val = 0;
#pragma unroll
            for (int o = 16; o; o >>= 1)
                val += __shfl_xor_sync(0xffffffffu, val, o);
            run += (int)val;
            if (ball) break;
            p -= 32;
        }
        if (t == 0) {
            atomicExch(&g_packed[b], (2ULL << 32) | (unsigned)(run + aggregate));
            sh_prefix = run;
        }
    }
    __syncthreads();

    if (gid < NNODES) {
        int r = sh_prefix + incl - d;
        g_rowstart[gid] = r;
        g_cursor[gid]   = r;
    }
    if (gid == 0) g_rowstart[NNODES] = NEDGES;
}

// ---------------- CSR fill: one int2 store per edge ---------------------------
__global__ void csrfill_kernel(const int* __restrict__ ei) {
    int e = blockIdx.x * blockDim.x + threadIdx.x;
    if (e < NB)  g_packed[e] = 0ULL;           // reset scan state for next replay
    if (e == NB) g_ticket = 0;
    if (e >= NEDGES) return;
    int s = ei[e];
    int d = ei[NEDGES + e];
    int pos = atomicAdd(&g_cursor[d], 1);
    float nrm = g_dinv[s] * g_dinv[d];
    g_csr[pos] = make_int2(s, __float_as_int(nrm));
}

// ---------------- single-shot fp16 GEMM (ldmatrix): [M,128] @ [128,128] -------
__global__ __launch_bounds__(256) void gemm128_f16_kernel(
    const float* __restrict__ A, const float* __restrict__ W,
    uint32_t* __restrict__ C, int M)
{
    extern __shared__ uint32_t sm[];
    uint32_t* xs = sm;             // [row 0..127][k2 0..63]  stride SR words
    uint32_t* wh = sm + 128 * SR;  // [k  0..127][n half2 0..63] stride SR words

    int tid  = threadIdx.x;
    int w    = tid >> 5;
    int lane = tid & 31;
    int g    = lane >> 2;
    int t4   = lane & 3;
    int r0   = blockIdx.x * 128;

#pragma unroll
    for (int L = tid; L < 4096; L += 256) {
        int r  = L >> 5;
        int kg = L & 31;
        int row = r0 + r;
        float4 v = make_float4(0.f, 0.f, 0.f, 0.f);
        if (row < M)
            v = *(const float4*)&A[(size_t)row * 128 + kg * 4];
        *(uint2*)&xs[r * SR + kg * 2] = make_uint2(pkh2(v.x, v.y), pkh2(v.z, v.w));
    }
#pragma unroll
    for (int L = tid; L < 4096; L += 256) {
        int k  = L >> 5;
        int ng = L & 31;
        float4 v = *(const float4*)&W[(size_t)k * 128 + ng * 4];
        *(uint2*)&wh[k * SR + ng * 2] = make_uint2(pkh2(v.x, v.y), pkh2(v.z, v.w));
    }
    __syncthreads();

    float acc[16][4];
#pragma unroll
    for (int j = 0; j < 16; j++)
#pragma unroll
        for (int i = 0; i < 4; i++) acc[j][i] = 0.f;

    uint32_t sbase = (uint32_t)__cvta_generic_to_shared(sm);
    uint32_t a_addr = sbase + (((w * 16 + (lane & 15)) * SR + ((lane >> 4) << 2)) << 2);
    uint32_t b_addr = sbase + ((128 * SR + (lane & 15) * SR + ((lane >> 4) << 2)) << 2);

#pragma unroll
    for (int m = 0; m < 8; m++) {
        uint32_t a0, a1, a2, a3;
        ldsm_x4(a0, a1, a2, a3, a_addr + m * 32);
        uint32_t bb = b_addr + m * 16 * SR * 4;
#pragma unroll
        for (int j = 0; j < 16; j += 2) {
            uint32_t b0, b1, b2, b3;
            ldsm_x4t(b0, b1, b2, b3, bb + j * 16);
            mma_f16(acc[j][0],   acc[j][1],   acc[j][2],   acc[j][3],
                    a0, a1, a2, a3, b0, b1);
            mma_f16(acc[j+1][0], acc[j+1][1], acc[j+1][2], acc[j+1][3],
                    a0, a1, a2, a3, b2, b3);
        }
    }

    int rowA = r0 + w * 16 + g;
#pragma unroll
    for (int j = 0; j < 16; j++) {
        if (rowA < M)
            C[(size_t)rowA * 64 + j * 4 + t4] = pkh2(acc[j][0], acc[j][1]);
        if (rowA + 8 < M)
            C[(size_t)(rowA + 8) * 64 + j * 4 + t4] = pkh2(acc[j][2], acc[j][3]);
    }
}

// ---------------- single-shot fp16 GEMM (ldmatrix): [M,128]half @ [128,40] ----
__global__ __launch_bounds__(256) void gemm40_f16_kernel(
    const uint32_t* __restrict__ Ah, const float* __restrict__ W,
    uint32_t* __restrict__ C, int M)
{
    extern __shared__ uint32_t sm[];
    uint32_t* xs = sm;
    uint32_t* wh = sm + 128 * SR;

    int tid  = threadIdx.x;
    int w    = tid >> 5;
    int lane = tid & 31;
    int g    = lane >> 2;
    int t4   = lane & 3;
    int r0   = blockIdx.x * 128;

#pragma unroll
    for (int L = tid; L < 2048; L += 256) {
        int r  = L >> 4;
        int kq = L & 15;
        int row = r0 + r;
        uint4 v = make_uint4(0u, 0u, 0u, 0u);
        if (row < M)
            v = *(const uint4*)&Ah[(size_t)row * 64 + kq * 4];
        *(uint4*)&xs[r * SR + kq * 4] = v;
    }
#pragma unroll
    for (int L = tid; L < 512; L += 256) {
        int k = L >> 2;
        wh[k * SR + 20 + (L & 3)] = 0u;
    }
#pragma unroll
    for (int L = tid; L < 1280; L += 256) {
        int k  = L / 10;
        int ng = L % 10;
        float4 v = *(const float4*)&W[(size_t)k * 40 + ng * 4];
        *(uint2*)&wh[k * SR + ng * 2] = make_uint2(pkh2(v.x, v.y), pkh2(v.z, v.w));
    }
    __syncthreads();

    float acc[6][4];
#pragma unroll
    for (int j = 0; j < 6; j++)
#pragma unroll
        for (int i = 0; i < 4; i++) acc[j][i] = 0.f;

    uint32_t sbase = (uint32_t)__cvta_generic_to_shared(sm);
    uint32_t a_addr = sbase + (((w * 16 + (lane & 15)) * SR + ((lane >> 4) << 2)) << 2);
    uint32_t b_addr = sbase + ((128 * SR + (lane & 15) * SR + ((lane >> 4) << 2)) << 2);

#pragma unroll
    for (int m = 0; m < 8; m++) {
        uint32_t a0, a1, a2, a3;
        ldsm_x4(a0, a1, a2, a3, a_addr + m * 32);
        uint32_t bb = b_addr + m * 16 * SR * 4;
#pragma unroll
        for (int j = 0; j < 6; j += 2) {
            uint32_t b0, b1, b2, b3;
            ldsm_x4t(b0, b1, b2, b3, bb + j * 16);
            mma_f16(acc[j][0],   acc[j][1],   acc[j][2],   acc[j][3],
                    a0, a1, a2, a3, b0, b1);
            mma_f16(acc[j+1][0], acc[j+1][1], acc[j+1][2], acc[j+1][3],
                    a0, a1, a2, a3, b2, b3);
        }
    }

    int rowA = r0 + w * 16 + g;
#pragma unroll
    for (int j = 0; j < 5; j++) {
        if (rowA < M)
            C[(size_t)rowA * 20 + j * 4 + t4] = pkh2(acc[j][0], acc[j][1]);
        if (rowA + 8 < M)
            C[(size_t)(rowA + 8) * 20 + j * 4 + t4] = pkh2(acc[j][2], acc[j][3]);
    }
}

// ---------------- gather layer 1 (C=128): half-warp per edge, uint4 loads -----
__global__ __launch_bounds__(256) void gather128_kernel(const float* __restrict__ b1) {
    int w = (blockIdx.x * blockDim.x + threadIdx.x) >> 5;
    if (w >= NNODES) return;
    int lane = threadIdx.x & 31;
    int half = lane >> 4;
    int sub  = lane & 15;

    int start = g_rowstart[w];
    int end   = g_rowstart[w + 1];

    const uint4* __restrict__ h4 = (const uint4*)g_h1h;   // 16B = 8 channels/lane
    float acc[8];
#pragma unroll
    for (int i = 0; i < 8; i++) acc[i] = 0.f;

    int j = start + half;
    for (; j + 2 < end; j += 4) {
        int2 e0 = __ldg(&g_csr[j]);
        int2 e1 = __ldg(&g_csr[j + 2]);
        uint4 u0 = h4[(size_t)e0.x * 16 + sub];
        uint4 u1 = h4[(size_t)e1.x * 16 + sub];
        acc8(acc, u0, __int_as_float(e0.y));
        acc8(acc, u1, __int_as_float(e1.y));
    }
    if (j < end) {
        int2 e0 = __ldg(&g_csr[j]);
        uint4 u0 = h4[(size_t)e0.x * 16 + sub];
        acc8(acc, u0, __int_as_float(e0.y));
    }

    // merge the two half-warps' partials (lane and lane^16 hold same channels)
#pragma unroll
    for (int i = 0; i < 8; i++)
        acc[i] += __shfl_xor_sync(0xffffffffu, acc[i], 16);

    // epilogue: self loop + bias + relu; half 0 writes
    float di = g_dinv[w];
    float d2 = di * di;
    uint4 us = h4[(size_t)w * 16 + sub];
    float hv[8];
    {
        float2 a;
        a = h2f2(us.x); hv[0] = a.x; hv[1] = a.y;
        a = h2f2(us.y); hv[2] = a.x; hv[3] = a.y;
        a = h2f2(us.z); hv[4] = a.x; hv[5] = a.y;
        a = h2f2(us.w); hv[6] = a.x; hv[7] = a.y;
    }
    float4 bb0 = ((const float4*)b1)[sub * 2];
    float4 bb1 = ((const float4*)b1)[sub * 2 + 1];
    float r[8];
    r[0] = fmaxf(fmaf(hv[0], d2, acc[0]) + bb0.x, 0.f);
    r[1] = fmaxf(fmaf(hv[1], d2, acc[1]) + bb0.y, 0.f);
    r[2] = fmaxf(fmaf(hv[2], d2, acc[2]) + bb0.z, 0.f);
    r[3] = fmaxf(fmaf(hv[3], d2, acc[3]) + bb0.w, 0.f);
    r[4] = fmaxf(fmaf(hv[4], d2, acc[4]) + bb1.x, 0.f);
    r[5] = fmaxf(fmaf(hv[5], d2, acc[5]) + bb1.y, 0.f);
    r[6] = fmaxf(fmaf(hv[6], d2, acc[6]) + bb1.z, 0.f);
    r[7] = fmaxf(fmaf(hv[7], d2, acc[7]) + bb1.w, 0.f);
    if (half == 0) {
        uint4 o = make_uint4(pkh2(r[0], r[1]), pkh2(r[2], r[3]),
                             pkh2(r[4], r[5]), pkh2(r[6], r[7]));
        ((uint4*)g_h1bh)[(size_t)w * 16 + sub] = o;
    }
}

// ---------------- gather layer 2 (C=40, fp16): two nodes per warp -------------
__global__ __launch_bounds__(256) void gather40_kernel(const float* __restrict__ b2,
                                                       float* __restrict__ out) {
    int w = (blockIdx.x * blockDim.x + threadIdx.x) >> 5;
    int lane = threadIdx.x & 31;
    int node = w * 2 + (lane >> 4);
    if (node >= NNODES) return;
    int sub = lane & 15;
    bool active = sub < 10;

    int start = g_rowstart[node];
    int end   = g_rowstart[node + 1];

    const uint2* __restrict__ h = (const uint2*)g_h2h;
    float4 acc = make_float4(0.f, 0.f, 0.f, 0.f);

    int j = start;
    for (; j + 1 < end; j += 2) {
        int2 e0 = __ldg(&g_csr[j]);
        int2 e1 = __ldg(&g_csr[j + 1]);
        if (active) {
            uint2 u0 = h[(size_t)e0.x * 10 + sub];
            uint2 u1 = h[(size_t)e1.x * 10 + sub];
            float n0 = __int_as_float(e0.y);
            float n1 = __int_as_float(e1.y);
            float2 a, b;
            a = h2f2(u0.x); b = h2f2(u0.y);
            acc.x = fmaf(n0, a.x, acc.x); acc.y = fmaf(n0, a.y, acc.y);
            acc.z = fmaf(n0, b.x, acc.z); acc.w = fmaf(n0, b.y, acc.w);
            a = h2f2(u1.x); b = h2f2(u1.y);
            acc.x = fmaf(n1, a.x, acc.x); acc.y = fmaf(n1, a.y, acc.y);
            acc.z = fmaf(n1, b.x, acc.z); acc.w = fmaf(n1, b.y, acc.w);
        }
    }
    if (j < end) {
        int2 e0 = __ldg(&g_csr[j]);
        if (active) {
            uint2 u0 = h[(size_t)e0.x * 10 + sub];
            float n0 = __int_as_float(e0.y);
            float2 a = h2f2(u0.x), b = h2f2(u0.y);
            acc.x = fmaf(n0, a.x, acc.x); acc.y = fmaf(n0, a.y, acc.y);
            acc.z = fmaf(n0, b.x, acc.z); acc.w = fmaf(n0, b.y, acc.w);
        }
    }

    if (active) {
        float di = g_dinv[node];
        float d2 = di * di;
        uint2 us = h[(size_t)node * 10 + sub];
        float2 ha = h2f2(us.x), hb = h2f2(us.y);
        float4 bb = ((const float4*)b2)[sub];
        float4 r;
        r.x = fmaf(ha.x, d2, acc.x) + bb.x;
        r.y = fmaf(ha.y, d2, acc.y) + bb.y;
        r.z = fmaf(hb.x, d2, acc.z) + bb.z;
        r.w = fmaf(hb.y, d2, acc.w) + bb.w;
        *(float4*)&out[(size_t)node * 40 + sub * 4] = r;
    }
}

// -----------------------------------------------------------------------------
extern "C" void kernel_launch(void* const* d_in, const int* in_sizes, int n_in,
                              void* d_out, int out_size) {
    const float* x   = (const float*)d_in[0];
    const int*   ei  = (const int*)  d_in[1];
    const float* W1  = (const float*)d_in[2];
    const float* b1  = (const float*)d_in[3];
    const float* W2  = (const float*)d_in[4];
    const float* b2  = (const float*)d_in[5];
    float* out = (float*)d_out;

    static bool s_init = false;
    static cudaStream_t s2;
    static cudaEvent_t evA, evB;
    if (!s_init) {   // host-side setup on first (uncaptured) call only
        cudaFuncSetAttribute(gemm128_f16_kernel,
                             cudaFuncAttributeMaxDynamicSharedMemorySize, GEMM_SMEM);
        cudaFuncSetAttribute(gemm40_f16_kernel,
                             cudaFuncAttributeMaxDynamicSharedMemorySize, GEMM_SMEM);
        cudaStreamCreateWithFlags(&s2, cudaStreamNonBlocking);
        cudaEventCreateWithFlags(&evA, cudaEventDisableTiming);
        cudaEventCreateWithFlags(&evB, cudaEventDisableTiming);
        s_init = true;
    }

    uint32_t* h1_p;  cudaGetSymbolAddress((void**)&h1_p,  g_h1h);
    uint32_t* h1b_p; cudaGetSymbolAddress((void**)&h1b_p, g_h1bh);
    uint32_t* h2_p;  cudaGetSymbolAddress((void**)&h2_p,  g_h2h);

    // ---- fork: CSR build on s2, concurrent with gemm128 on main stream ----
    cudaEventRecord(evA, 0);
    cudaStreamWaitEvent(s2, evA, 0);
    degree_kernel<<<(NEDGES / 2 + 255) / 256, 256, 0, s2>>>(ei);
    scan_fused_kernel<<<NB, 256, 0, s2>>>();
    csrfill_kernel<<<(NEDGES + 255) / 256, 256, 0, s2>>>(ei);
    cudaEventRecord(evB, s2);

    gemm128_f16_kernel<<<(NNODES + 127) / 128, 256, GEMM_SMEM>>>(x, W1, h1_p, NNODES);

    // ---- join, then the dependent chain ----
    cudaStreamWaitEvent(0, evB, 0);
    gather128_kernel<<<(NNODES * 32 + 255) / 256, 256>>>(b1);
    gemm40_f16_kernel<<<(NNODES + 127) / 128, 256, GEMM_SMEM>>>(h1b_p, W2, h2_p, NNODES);
    gather40_kernel<<<((NNODES + 1) / 2 * 32 + 255) / 256, 256>>>(b2, out);
}